// round 6
// baseline (speedup 1.0000x reference)
#include <cuda_runtime.h>
#include <cuda_fp16.h>
#include <mma.h>
#include <math.h>
#include <stdint.h>

using namespace nvcuda;

#define Bb    2
#define SEQ   2048
#define Hh    1024
#define NHd   16
#define Dd    64
#define Mtok  4096

// fp32 scratch: qlin,klin,vlin
__device__ float  g_f32[(size_t)3 * Mtok * Hh];
// half scratch: hs_h(4M) Wq,Wk,Wv,Wo(1M ea) qT,kT,vT(4M ea) attn(4M)
__device__ __half g_f16[(size_t)(4 + 4 + 12 + 4) * 1024 * 1024];

__device__ __forceinline__ void cp_async16(void* smem, const void* gmem) {
    unsigned saddr = (unsigned)__cvta_generic_to_shared(smem);
    asm volatile("cp.async.cg.shared.global [%0], [%1], 16;\n" :: "r"(saddr), "l"(gmem));
}
__device__ __forceinline__ void cp_commit() { asm volatile("cp.async.commit_group;\n"); }
template <int N>
__device__ __forceinline__ void cp_wait() { asm volatile("cp.async.wait_group %0;\n" :: "n"(N)); }

// ---------------------------------------------------------------------------
// fused fp32->fp16: hs (4M) + Wq,Wk,Wv,Wo (1M each) -> contiguous g_f16 base
// ---------------------------------------------------------------------------
#define SZc ((size_t)Mtok * Hh)      // 4M
#define WZc ((size_t)Hh * Hh)        // 1M
__global__ __launch_bounds__(256)
void f2h_all_kernel(const float* __restrict__ hs,
                    const float* __restrict__ Wq, const float* __restrict__ Wk,
                    const float* __restrict__ Wv, const float* __restrict__ Wo,
                    __half* __restrict__ dst)
{
    size_t i4 = ((size_t)blockIdx.x * 256 + threadIdx.x) * 4;
    const float* s;
    if (i4 < SZc) s = &hs[i4];
    else {
        size_t wo = i4 - SZc;
        s = (wo < WZc)     ? &Wq[wo]
          : (wo < 2 * WZc) ? &Wk[wo - WZc]
          : (wo < 3 * WZc) ? &Wv[wo - 2 * WZc]
                           : &Wo[wo - 3 * WZc];
    }
    float4 v = *(const float4*)s;
    *(__half2*)&dst[i4]     = __floats2half2_rn(v.x, v.y);
    *(__half2*)&dst[i4 + 2] = __floats2half2_rn(v.z, v.w);
}

// ---------------------------------------------------------------------------
// fp16 GEMM: C[M,N] = A[M,K] @ W[N,K]^T (fp32 accum/out).
// 128x128 tile, BK=64, 2-stage cp.async, 256 threads, 8 warps of 32x64.
// gridDim.z selects (W,C) to fuse QKV. bias!=null -> smem epilogue with bias.
// ---------------------------------------------------------------------------
#define GBK  64
#define GLD2 72                   // halfs; 144B row stride
#define GSTG (128 * GLD2)         // halfs per matrix per stage
#define GEMM_SMEM (4 * GSTG * 2)  // bytes (2 stages x A,B) = 73728
#define CLD 132                   // epilogue fp32 row stride

__global__ __launch_bounds__(256)
void gemm_fp16_kernel(const __half* __restrict__ A,
                      const __half* __restrict__ W0, const __half* __restrict__ W1,
                      const __half* __restrict__ W2,
                      float* __restrict__ C0, float* __restrict__ C1, float* __restrict__ C2,
                      const float* __restrict__ bias)
{
    extern __shared__ __align__(16) __half gsm[];
    __half* As = gsm;                 // [2][GSTG]
    __half* Bs = gsm + 2 * GSTG;      // [2][GSTG]

    const __half* W = (blockIdx.z == 0) ? W0 : (blockIdx.z == 1) ? W1 : W2;
    float*        C = (blockIdx.z == 0) ? C0 : (blockIdx.z == 1) ? C1 : C2;

    const int tid = threadIdx.x;
    const int bm = blockIdx.y * 128, bn = blockIdx.x * 128;
    const int w  = tid >> 5;
    const int wr = w & 3;             // 4 row warps (32 rows)
    const int wc = w >> 2;            // 2 col warps (64 cols)
    const int K = 1024;

    wmma::fragment<wmma::accumulator, 16, 16, 16, float> acc[2][4];
    #pragma unroll
    for (int i = 0; i < 2; i++)
        #pragma unroll
        for (int j = 0; j < 4; j++) wmma::fill_fragment(acc[i][j], 0.0f);

    const int lr = tid >> 1;              // 0..127
    const int lc = (tid & 1) * 32;        // half-col base; 4 chunks of 8 halfs

    // prefetch stage 0
    #pragma unroll
    for (int i = 0; i < 4; i++) {
        int c8 = lc + i * 8;
        cp_async16(&As[lr * GLD2 + c8], &A[(size_t)(bm + lr) * K + c8]);
        cp_async16(&Bs[lr * GLD2 + c8], &W[(size_t)(bn + lr) * K + c8]);
    }
    cp_commit();

    const int niter = K / GBK;            // 16
    for (int it = 0; it < niter; it++) {
        const int s = it & 1;
        if (it + 1 < niter) {
            const int k0 = (it + 1) * GBK;
            __half* Ad = &As[(s ^ 1) * GSTG];
            __half* Bd = &Bs[(s ^ 1) * GSTG];
            #pragma unroll
            for (int i = 0; i < 4; i++) {
                int c8 = lc + i * 8;
                cp_async16(&Ad[lr * GLD2 + c8], &A[(size_t)(bm + lr) * K + k0 + c8]);
                cp_async16(&Bd[lr * GLD2 + c8], &W[(size_t)(bn + lr) * K + k0 + c8]);
            }
            cp_commit();
            cp_wait<1>();
        } else {
            cp_wait<0>();
        }
        __syncthreads();

        const __half* Ac = &As[s * GSTG];
        const __half* Bc = &Bs[s * GSTG];
        #pragma unroll
        for (int kk = 0; kk < 4; kk++) {
            const int kd = kk * 16;
            wmma::fragment<wmma::matrix_a, 16, 16, 16, __half, wmma::row_major> a0, a1;
            wmma::load_matrix_sync(a0, &Ac[(wr * 32     ) * GLD2 + kd], GLD2);
            wmma::load_matrix_sync(a1, &Ac[(wr * 32 + 16) * GLD2 + kd], GLD2);
            #pragma unroll
            for (int nt = 0; nt < 4; nt++) {
                wmma::fragment<wmma::matrix_b, 16, 16, 16, __half, wmma::col_major> b;
                wmma::load_matrix_sync(b, &Bc[(wc * 64 + nt * 16) * GLD2 + kd], GLD2);
                wmma::mma_sync(acc[0][nt], a0, b, acc[0][nt]);
                wmma::mma_sync(acc[1][nt], a1, b, acc[1][nt]);
            }
        }
        __syncthreads();
    }

    if (bias == nullptr) {
        #pragma unroll
        for (int i = 0; i < 2; i++)
            #pragma unroll
            for (int j = 0; j < 4; j++) {
                int row = bm + wr * 32 + i * 16;
                int col = bn + wc * 64 + j * 16;
                wmma::store_matrix_sync(&C[(size_t)row * 1024 + col], acc[i][j], 1024,
                                        wmma::mem_row_major);
            }
    } else {
        // smem epilogue: add bias, coalesced float4 stores
        float* Cs = (float*)gsm;          // 128 x CLD (67584 B <= 73728)
        #pragma unroll
        for (int i = 0; i < 2; i++)
            #pragma unroll
            for (int j = 0; j < 4; j++)
                wmma::store_matrix_sync(&Cs[(wr * 32 + i * 16) * CLD + wc * 64 + j * 16],
                                        acc[i][j], CLD, wmma::mem_row_major);
        __syncthreads();
        const int row = tid >> 1;
        const int cb  = (tid & 1) * 64;
        float* dst = &C[(size_t)(bm + row) * 1024 + bn + cb];
        const float* src = &Cs[row * CLD + cb];
        const float* bp = &bias[bn + cb];
        #pragma unroll
        for (int j = 0; j < 64; j += 4) {
            float4 o = *(const float4*)&src[j];
            o.x += bp[j]; o.y += bp[j + 1]; o.z += bp[j + 2]; o.w += bp[j + 3];
            *(float4*)&dst[j] = o;
        }
    }
}

// ---------------------------------------------------------------------------
// RMSNorm + bias + RoPE; outputs HALF q/k/v in [B,NH,S,D]; q pre-scaled 1/8.
// ---------------------------------------------------------------------------
__global__ __launch_bounds__(256)
void normrope_kernel(const float* __restrict__ qlin, const float* __restrict__ klin,
                     const float* __restrict__ vlin,
                     const float* __restrict__ bq, const float* __restrict__ bk,
                     const float* __restrict__ bv,
                     const float* __restrict__ cosT, const float* __restrict__ sinT,
                     const float* __restrict__ w,
                     __half* __restrict__ qo, __half* __restrict__ ko, __half* __restrict__ vo)
{
    const int t = blockIdx.x;
    const int b = t >> 11;
    const int s = t & 2047;
    const int tid = threadIdx.x;

    __shared__ float sq[1024], sk[1024];
    __shared__ float red[16];
    __shared__ float rqs, rks;

    float sumq = 0.f, sumk = 0.f;
    for (int i = tid; i < 1024; i += 256) {
        float x = qlin[(size_t)t * 1024 + i] + bq[i]; sq[i] = x; sumq += x * x;
        float y = klin[(size_t)t * 1024 + i] + bk[i]; sk[i] = y; sumk += y * y;
    }
    #pragma unroll
    for (int off = 16; off > 0; off >>= 1) {
        sumq += __shfl_down_sync(0xffffffffu, sumq, off);
        sumk += __shfl_down_sync(0xffffffffu, sumk, off);
    }
    if ((tid & 31) == 0) { red[tid >> 5] = sumq; red[8 + (tid >> 5)] = sumk; }
    __syncthreads();
    if (tid == 0) {
        float a = 0.f, c = 0.f;
        #pragma unroll
        for (int i2 = 0; i2 < 8; i2++) { a += red[i2]; c += red[8 + i2]; }
        rqs = rsqrtf(a * (1.0f / 1024.0f) + 1e-6f);
        rks = rsqrtf(c * (1.0f / 1024.0f) + 1e-6f);
    }
    __syncthreads();
    const float rq = rqs, rk = rks;

    for (int i = tid; i < 1024; i += 256) {
        int h = i >> 6, d = i & 63;
        float cs = cosT[s * 64 + d], sn = sinT[s * 64 + d];
        int   pi = (d < 32) ? i + 32 : i - 32;
        float sign = (d < 32) ? -1.f : 1.f;
        float wv = w[i], wp = w[pi];
        float qv = sq[i] * rq * wv, qp = sq[pi] * rq * wp;
        float kv = sk[i] * rk * wv, kp = sk[pi] * rk * wp;
        size_t oidx = ((size_t)(b * NHd + h) * SEQ + s) * Dd + d;
        qo[oidx] = __float2half((qv * cs + sign * qp * sn) * 0.125f);
        ko[oidx] = __float2half(kv * cs + sign * kp * sn);
        vo[oidx] = __float2half(vlin[(size_t)t * 1024 + i] + bv[i]);
    }
}

// ---------------------------------------------------------------------------
// Flash attention, fp16 wmma, no running max (|scores| <= 9, -3 shift cancels).
// K/V tiles double-buffered via cp.async. 128 queries x 1 (b,h), 8 warps.
// ---------------------------------------------------------------------------
#define FLDH 72
#define FLDS 72
#define FSTG (64 * FLDH)      // halfs per K (or V) stage
#define FSM_BYTES (4 * FSTG * 2 + 128 * FLDS * 4 + 128 * FLDH * 2)   // 92160

__global__ __launch_bounds__(256)
void flash_fp16_kernel(const __half* __restrict__ q, const __half* __restrict__ k,
                       const __half* __restrict__ v, __half* __restrict__ out)
{
    extern __shared__ __align__(16) char smraw[];
    __half* Ks = (__half*)smraw;                       // [2][FSTG]
    __half* Vs = Ks + 2 * FSTG;                        // [2][FSTG]
    float*  Sp = (float*)(Vs + 2 * FSTG);              // [128][FLDS]
    __half* Ph = (__half*)(Sp + 128 * FLDS);           // [128][FLDH]

    const int tid = threadIdx.x;
    const int w   = tid >> 5;
    const int bh  = blockIdx.y;
    const int qt  = blockIdx.x;
    const __half* kb = k + (size_t)bh * SEQ * Dd;
    const __half* vb = v + (size_t)bh * SEQ * Dd;

    wmma::fragment<wmma::matrix_a, 16, 16, 16, __half, wmma::row_major> qfrag[4];
    {
        const __half* qptr = q + ((size_t)bh * SEQ + qt * 128 + w * 16) * Dd;
        #pragma unroll
        for (int kk = 0; kk < 4; kk++)
            wmma::load_matrix_sync(qfrag[kk], qptr + kk * 16, Dd);
    }

    wmma::fragment<wmma::accumulator, 16, 16, 16, float> oacc[4];
    #pragma unroll
    for (int nt = 0; nt < 4; nt++) wmma::fill_fragment(oacc[nt], 0.0f);

    const int row  = tid >> 1;
    const int half = tid & 1;
    const int qrow = qt * 128 + row;
    float l_priv = 0.f;

    // loader mapping: 2 chunks of K + 2 chunks of V per thread per stage
    const int lr  = tid >> 2;            // 0..63
    const int lc8 = (tid & 3) << 4;      // 0,16,32,48

    // prefetch tile 0
    #pragma unroll
    for (int i = 0; i < 2; i++) {
        int c8 = lc8 + i * 8;
        cp_async16(&Ks[lr * FLDH + c8], &kb[(size_t)lr * Dd + c8]);
        cp_async16(&Vs[lr * FLDH + c8], &vb[(size_t)lr * Dd + c8]);
    }
    cp_commit();

    const int NT = SEQ / 64;
    for (int t = 0; t < NT; t++) {
        const int s = t & 1;
        const int kt = t * 64;
        if (t + 1 < NT) {
            const int kn = kt + 64;
            __half* Kd = &Ks[(s ^ 1) * FSTG];
            __half* Vd = &Vs[(s ^ 1) * FSTG];
            #pragma unroll
            for (int i = 0; i < 2; i++) {
                int c8 = lc8 + i * 8;
                cp_async16(&Kd[lr * FLDH + c8], &kb[(size_t)(kn + lr) * Dd + c8]);
                cp_async16(&Vd[lr * FLDH + c8], &vb[(size_t)(kn + lr) * Dd + c8]);
            }
            cp_commit();
            cp_wait<1>();
        } else {
            cp_wait<0>();
        }
        __syncthreads();

        const __half* Kc = &Ks[s * FSTG];
        const __half* Vc = &Vs[s * FSTG];

        // S = Q @ K^T (16x64 per warp)
        wmma::fragment<wmma::accumulator, 16, 16, 16, float> sfr[4];
        #pragma unroll
        for (int nt = 0; nt < 4; nt++) wmma::fill_fragment(sfr[nt], 0.0f);
        #pragma unroll
        for (int kk = 0; kk < 4; kk++) {
            const int kd = kk * 16;
            #pragma unroll
            for (int nt = 0; nt < 4; nt++) {
                wmma::fragment<wmma::matrix_b, 16, 16, 16, __half, wmma::col_major> bfr;
                wmma::load_matrix_sync(bfr, &Kc[(nt * 16) * FLDH + kd], FLDH);
                wmma::mma_sync(sfr[nt], qfrag[kk], bfr, sfr[nt]);
            }
        }
        #pragma unroll
        for (int nt = 0; nt < 4; nt++)
            wmma::store_matrix_sync(&Sp[(w * 16) * FLDS + nt * 16], sfr[nt], FLDS,
                                    wmma::mem_row_major);
        __syncwarp();

        // P = exp(S + tril - 3) -> half; accumulate l
        {
            float*  srow = &Sp[row * FLDS + half * 32];
            __half* prow = &Ph[row * FLDH + half * 32];
            float psum = 0.f;
            #pragma unroll
            for (int c = 0; c < 32; c += 4) {
                float4 s4 = *(float4*)&srow[c];
                int col = kt + half * 32 + c;
                float p0 = __expf(s4.x - 3.0f + ((col + 0) <= qrow ? 1.0f : 0.0f));
                float p1 = __expf(s4.y - 3.0f + ((col + 1) <= qrow ? 1.0f : 0.0f));
                float p2 = __expf(s4.z - 3.0f + ((col + 2) <= qrow ? 1.0f : 0.0f));
                float p3 = __expf(s4.w - 3.0f + ((col + 3) <= qrow ? 1.0f : 0.0f));
                *(__half2*)&prow[c]     = __floats2half2_rn(p0, p1);
                *(__half2*)&prow[c + 2] = __floats2half2_rn(p2, p3);
                psum += (p0 + p1) + (p2 + p3);
            }
            l_priv += psum;
        }
        __syncwarp();

        // O += P @ V
        #pragma unroll
        for (int kk = 0; kk < 4; kk++) {
            wmma::fragment<wmma::matrix_a, 16, 16, 16, __half, wmma::row_major> afr;
            wmma::load_matrix_sync(afr, &Ph[(w * 16) * FLDH + kk * 16], FLDH);
            #pragma unroll
            for (int nt = 0; nt < 4; nt++) {
                wmma::fragment<wmma::matrix_b, 16, 16, 16, __half, wmma::row_major> vfr;
                wmma::load_matrix_sync(vfr, &Vc[(kk * 16) * FLDH + nt * 16], FLDH);
                wmma::mma_sync(oacc[nt], afr, vfr, oacc[nt]);
            }
        }
        __syncthreads();
    }

    #pragma unroll
    for (int nt = 0; nt < 4; nt++)
        wmma::store_matrix_sync(&Sp[(w * 16) * FLDS + nt * 16], oacc[nt], FLDS,
                                wmma::mem_row_major);
    __syncwarp();
    {
        float l_tot = l_priv + __shfl_xor_sync(0xffffffffu, l_priv, 1);
        float invl = 1.f / l_tot;
        const int b = bh >> 4, h = bh & 15;
        const float* orow = &Sp[row * FLDS + half * 32];
        __half* dst = out + ((size_t)(b * SEQ + qt * 128 + row)) * Hh + h * Dd + half * 32;
        #pragma unroll
        for (int c = 0; c < 32; c += 4) {
            float4 t = *(const float4*)&orow[c];
            *(__half2*)&dst[c]     = __floats2half2_rn(t.x * invl, t.y * invl);
            *(__half2*)&dst[c + 2] = __floats2half2_rn(t.z * invl, t.w * invl);
        }
    }
}

// ---------------------------------------------------------------------------
extern "C" void kernel_launch(void* const* d_in, const int* in_sizes, int n_in,
                              void* d_out, int out_size)
{
    const float* hs   = (const float*)d_in[0];
    const float* cosT = (const float*)d_in[1];
    const float* sinT = (const float*)d_in[2];
    const float* Wq   = (const float*)d_in[3];
    const float* bq   = (const float*)d_in[4];
    const float* Wk   = (const float*)d_in[5];
    const float* bk   = (const float*)d_in[6];
    const float* Wv   = (const float*)d_in[7];
    const float* bv   = (const float*)d_in[8];
    const float* Wo   = (const float*)d_in[9];
    const float* bo   = (const float*)d_in[10];
    const float* rw   = (const float*)d_in[11];
    float* out = (float*)d_out;

    float* f32 = nullptr;  cudaGetSymbolAddress((void**)&f32, g_f32);
    __half* f16 = nullptr; cudaGetSymbolAddress((void**)&f16, g_f16);

    const size_t SZ = SZc;                     // 4M
    const size_t WZ = WZc;                     // 1M
    float* qlin = f32;
    float* klin = f32 + SZ;
    float* vlin = f32 + 2 * SZ;

    __half* hs_h  = f16;
    __half* Wq_h  = f16 + SZ;                  // weights contiguous after hs
    __half* Wk_h  = Wq_h + WZ;
    __half* Wv_h  = Wk_h + WZ;
    __half* Wo_h  = Wv_h + WZ;
    __half* qT    = Wo_h + WZ;
    __half* kT    = qT + SZ;
    __half* vT    = kT + SZ;
    __half* attn  = vT + SZ;

    cudaFuncSetAttribute(flash_fp16_kernel,
                         cudaFuncAttributeMaxDynamicSharedMemorySize, FSM_BYTES);
    cudaFuncSetAttribute(gemm_fp16_kernel,
                         cudaFuncAttributeMaxDynamicSharedMemorySize, GEMM_SMEM);

    // 8M elements total (hs + 4 weights), 4 per thread
    f2h_all_kernel<<<(int)((SZ + 4 * WZ) / 1024), 256>>>(hs, Wq, Wk, Wv, Wo, f16);

    dim3 gqkv(Hh / 128, Mtok / 128, 3);
    gemm_fp16_kernel<<<gqkv, 256, GEMM_SMEM>>>(hs_h, Wq_h, Wk_h, Wv_h,
                                               qlin, klin, vlin, nullptr);

    normrope_kernel<<<Mtok, 256>>>(qlin, klin, vlin, bq, bk, bv,
                                   cosT, sinT, rw, qT, kT, vT);

    dim3 fg(SEQ / 128, Bb * NHd);
    flash_fp16_kernel<<<fg, 256, FSM_BYTES>>>(qT, kT, vT, attn);

    dim3 gout(Hh / 128, Mtok / 128, 1);
    gemm_fp16_kernel<<<gout, 256, GEMM_SMEM>>>(attn, Wo_h, Wo_h, Wo_h,
                                               out, out, out, bo);
}

// round 7
// speedup vs baseline: 1.1830x; 1.1830x over previous
#include <cuda_runtime.h>
#include <cuda_fp16.h>
#include <mma.h>
#include <math.h>
#include <stdint.h>

using namespace nvcuda;

#define Bb    2
#define SEQ   2048
#define Hh    1024
#define NHd   16
#define Dd    64
#define Mtok  4096

__device__ float  g_f32[(size_t)3 * Mtok * Hh];
__device__ __half g_f16[(size_t)(4 + 4 + 12 + 4) * 1024 * 1024];

__device__ __forceinline__ void cp_async16(void* smem, const void* gmem) {
    unsigned saddr = (unsigned)__cvta_generic_to_shared(smem);
    asm volatile("cp.async.cg.shared.global [%0], [%1], 16;\n" :: "r"(saddr), "l"(gmem));
}
__device__ __forceinline__ void cp_commit() { asm volatile("cp.async.commit_group;\n"); }
template <int N>
__device__ __forceinline__ void cp_wait() { asm volatile("cp.async.wait_group %0;\n" :: "n"(N)); }

__device__ __forceinline__ void ldsm_x4(uint32_t* r, uint32_t saddr) {
    asm volatile("ldmatrix.sync.aligned.m8n8.x4.shared.b16 {%0,%1,%2,%3}, [%4];"
                 : "=r"(r[0]), "=r"(r[1]), "=r"(r[2]), "=r"(r[3]) : "r"(saddr));
}
__device__ __forceinline__ void ldsm_x4_t(uint32_t* r, uint32_t saddr) {
    asm volatile("ldmatrix.sync.aligned.m8n8.x4.trans.shared.b16 {%0,%1,%2,%3}, [%4];"
                 : "=r"(r[0]), "=r"(r[1]), "=r"(r[2]), "=r"(r[3]) : "r"(saddr));
}
__device__ __forceinline__ void mma16816(float* c, const uint32_t* a, const uint32_t* b) {
    asm volatile(
        "mma.sync.aligned.m16n8k16.row.col.f32.f16.f16.f32 "
        "{%0,%1,%2,%3}, {%4,%5,%6,%7}, {%8,%9}, {%0,%1,%2,%3};"
        : "+f"(c[0]), "+f"(c[1]), "+f"(c[2]), "+f"(c[3])
        : "r"(a[0]), "r"(a[1]), "r"(a[2]), "r"(a[3]), "r"(b[0]), "r"(b[1]));
}
__device__ __forceinline__ uint32_t packh2(float x, float y) {
    __half2 h = __floats2half2_rn(x, y);
    return *(uint32_t*)&h;
}

// ---------------------------------------------------------------------------
// fused fp32->fp16 conversion
// ---------------------------------------------------------------------------
#define SZc ((size_t)Mtok * Hh)
#define WZc ((size_t)Hh * Hh)
__global__ __launch_bounds__(256)
void f2h_all_kernel(const float* __restrict__ hs,
                    const float* __restrict__ Wq, const float* __restrict__ Wk,
                    const float* __restrict__ Wv, const float* __restrict__ Wo,
                    __half* __restrict__ dst)
{
    size_t i4 = ((size_t)blockIdx.x * 256 + threadIdx.x) * 4;
    const float* s;
    if (i4 < SZc) s = &hs[i4];
    else {
        size_t wo = i4 - SZc;
        s = (wo < WZc)     ? &Wq[wo]
          : (wo < 2 * WZc) ? &Wk[wo - WZc]
          : (wo < 3 * WZc) ? &Wv[wo - 2 * WZc]
                           : &Wo[wo - 3 * WZc];
    }
    float4 v = *(const float4*)s;
    *(__half2*)&dst[i4]     = __floats2half2_rn(v.x, v.y);
    *(__half2*)&dst[i4 + 2] = __floats2half2_rn(v.z, v.w);
}

// ---------------------------------------------------------------------------
// fp16 GEMM (wmma): 128x128 tile, BK=64, 2-stage cp.async, 256 threads.
// ---------------------------------------------------------------------------
#define GBK  64
#define GLD2 72
#define GSTG (128 * GLD2)
#define GEMM_SMEM (4 * GSTG * 2)
#define CLD 132

__global__ __launch_bounds__(256)
void gemm_fp16_kernel(const __half* __restrict__ A,
                      const __half* __restrict__ W0, const __half* __restrict__ W1,
                      const __half* __restrict__ W2,
                      float* __restrict__ C0, float* __restrict__ C1, float* __restrict__ C2,
                      const float* __restrict__ bias)
{
    extern __shared__ __align__(16) __half gsm[];
    __half* As = gsm;
    __half* Bs = gsm + 2 * GSTG;

    const __half* W = (blockIdx.z == 0) ? W0 : (blockIdx.z == 1) ? W1 : W2;
    float*        C = (blockIdx.z == 0) ? C0 : (blockIdx.z == 1) ? C1 : C2;

    const int tid = threadIdx.x;
    const int bm = blockIdx.y * 128, bn = blockIdx.x * 128;
    const int w  = tid >> 5;
    const int wr = w & 3;
    const int wc = w >> 2;
    const int K = 1024;

    wmma::fragment<wmma::accumulator, 16, 16, 16, float> acc[2][4];
    #pragma unroll
    for (int i = 0; i < 2; i++)
        #pragma unroll
        for (int j = 0; j < 4; j++) wmma::fill_fragment(acc[i][j], 0.0f);

    const int lr = tid >> 1;
    const int lc = (tid & 1) * 32;

    #pragma unroll
    for (int i = 0; i < 4; i++) {
        int c8 = lc + i * 8;
        cp_async16(&As[lr * GLD2 + c8], &A[(size_t)(bm + lr) * K + c8]);
        cp_async16(&Bs[lr * GLD2 + c8], &W[(size_t)(bn + lr) * K + c8]);
    }
    cp_commit();

    const int niter = K / GBK;
    for (int it = 0; it < niter; it++) {
        const int s = it & 1;
        if (it + 1 < niter) {
            const int k0 = (it + 1) * GBK;
            __half* Ad = &As[(s ^ 1) * GSTG];
            __half* Bd = &Bs[(s ^ 1) * GSTG];
            #pragma unroll
            for (int i = 0; i < 4; i++) {
                int c8 = lc + i * 8;
                cp_async16(&Ad[lr * GLD2 + c8], &A[(size_t)(bm + lr) * K + k0 + c8]);
                cp_async16(&Bd[lr * GLD2 + c8], &W[(size_t)(bn + lr) * K + k0 + c8]);
            }
            cp_commit();
            cp_wait<1>();
        } else {
            cp_wait<0>();
        }
        __syncthreads();

        const __half* Ac = &As[s * GSTG];
        const __half* Bc = &Bs[s * GSTG];
        #pragma unroll
        for (int kk = 0; kk < 4; kk++) {
            const int kd = kk * 16;
            wmma::fragment<wmma::matrix_a, 16, 16, 16, __half, wmma::row_major> a0, a1;
            wmma::load_matrix_sync(a0, &Ac[(wr * 32     ) * GLD2 + kd], GLD2);
            wmma::load_matrix_sync(a1, &Ac[(wr * 32 + 16) * GLD2 + kd], GLD2);
            #pragma unroll
            for (int nt = 0; nt < 4; nt++) {
                wmma::fragment<wmma::matrix_b, 16, 16, 16, __half, wmma::col_major> b;
                wmma::load_matrix_sync(b, &Bc[(wc * 64 + nt * 16) * GLD2 + kd], GLD2);
                wmma::mma_sync(acc[0][nt], a0, b, acc[0][nt]);
                wmma::mma_sync(acc[1][nt], a1, b, acc[1][nt]);
            }
        }
        __syncthreads();
    }

    if (bias == nullptr) {
        #pragma unroll
        for (int i = 0; i < 2; i++)
            #pragma unroll
            for (int j = 0; j < 4; j++) {
                int row = bm + wr * 32 + i * 16;
                int col = bn + wc * 64 + j * 16;
                wmma::store_matrix_sync(&C[(size_t)row * 1024 + col], acc[i][j], 1024,
                                        wmma::mem_row_major);
            }
    } else {
        float* Cs = (float*)gsm;
        #pragma unroll
        for (int i = 0; i < 2; i++)
            #pragma unroll
            for (int j = 0; j < 4; j++)
                wmma::store_matrix_sync(&Cs[(wr * 32 + i * 16) * CLD + wc * 64 + j * 16],
                                        acc[i][j], CLD, wmma::mem_row_major);
        __syncthreads();
        const int row = tid >> 1;
        const int cb  = (tid & 1) * 64;
        float* dst = &C[(size_t)(bm + row) * 1024 + bn + cb];
        const float* src = &Cs[row * CLD + cb];
        const float* bp = &bias[bn + cb];
        #pragma unroll
        for (int j = 0; j < 64; j += 4) {
            float4 o = *(const float4*)&src[j];
            o.x += bp[j]; o.y += bp[j + 1]; o.z += bp[j + 2]; o.w += bp[j + 3];
            *(float4*)&dst[j] = o;
        }
    }
}

// ---------------------------------------------------------------------------
// RMSNorm + bias + RoPE -> half q/k/v in [B,NH,S,D]; q pre-scaled 1/8.
// ---------------------------------------------------------------------------
__global__ __launch_bounds__(256)
void normrope_kernel(const float* __restrict__ qlin, const float* __restrict__ klin,
                     const float* __restrict__ vlin,
                     const float* __restrict__ bq, const float* __restrict__ bk,
                     const float* __restrict__ bv,
                     const float* __restrict__ cosT, const float* __restrict__ sinT,
                     const float* __restrict__ w,
                     __half* __restrict__ qo, __half* __restrict__ ko, __half* __restrict__ vo)
{
    const int t = blockIdx.x;
    const int b = t >> 11;
    const int s = t & 2047;
    const int tid = threadIdx.x;

    __shared__ float sq[1024], sk[1024];
    __shared__ float red[16];
    __shared__ float rqs, rks;

    float sumq = 0.f, sumk = 0.f;
    for (int i = tid; i < 1024; i += 256) {
        float x = qlin[(size_t)t * 1024 + i] + bq[i]; sq[i] = x; sumq += x * x;
        float y = klin[(size_t)t * 1024 + i] + bk[i]; sk[i] = y; sumk += y * y;
    }
    #pragma unroll
    for (int off = 16; off > 0; off >>= 1) {
        sumq += __shfl_down_sync(0xffffffffu, sumq, off);
        sumk += __shfl_down_sync(0xffffffffu, sumk, off);
    }
    if ((tid & 31) == 0) { red[tid >> 5] = sumq; red[8 + (tid >> 5)] = sumk; }
    __syncthreads();
    if (tid == 0) {
        float a = 0.f, c = 0.f;
        #pragma unroll
        for (int i2 = 0; i2 < 8; i2++) { a += red[i2]; c += red[8 + i2]; }
        rqs = rsqrtf(a * (1.0f / 1024.0f) + 1e-6f);
        rks = rsqrtf(c * (1.0f / 1024.0f) + 1e-6f);
    }
    __syncthreads();
    const float rq = rqs, rk = rks;

    for (int i = tid; i < 1024; i += 256) {
        int h = i >> 6, d = i & 63;
        float cs = cosT[s * 64 + d], sn = sinT[s * 64 + d];
        int   pi = (d < 32) ? i + 32 : i - 32;
        float sign = (d < 32) ? -1.f : 1.f;
        float wv = w[i], wp = w[pi];
        float qv = sq[i] * rq * wv, qp = sq[pi] * rq * wp;
        float kv = sk[i] * rk * wv, kp = sk[pi] * rk * wp;
        size_t oidx = ((size_t)(b * NHd + h) * SEQ + s) * Dd + d;
        qo[oidx] = __float2half((qv * cs + sign * qp * sn) * 0.125f);
        ko[oidx] = __float2half(kv * cs + sign * kp * sn);
        vo[oidx] = __float2half(vlin[(size_t)t * 1024 + i] + bv[i]);
    }
}

// ---------------------------------------------------------------------------
// Flash attention with raw mma.sync.m16n8k16 — S/P fully register-resident.
// Block: 128 queries x 1 (b,h), 8 warps (16 q-rows each). No running max
// (|scores| <= ~10; constant -3 shift cancels in O = P@V / l).
// smem: Q[128][72] + K[2][64][72] + V[2][64][72] halfs = 55296 B.
// ---------------------------------------------------------------------------
#define QLD 72
#define FTILE (64 * QLD)          // halfs per K/V stage
#define FSM_BYTES ((128 * QLD + 4 * FTILE) * 2)

__global__ __launch_bounds__(256, 2)
void flash_mma_kernel(const __half* __restrict__ q, const __half* __restrict__ k,
                      const __half* __restrict__ v, __half* __restrict__ out)
{
    extern __shared__ __align__(16) char smraw[];
    __half* Qs = (__half*)smraw;               // [128][QLD]
    __half* Ks = Qs + 128 * QLD;               // [2][64][QLD]
    __half* Vs = Ks + 2 * FTILE;               // [2][64][QLD]

    const int tid  = threadIdx.x;
    const int w    = tid >> 5;
    const int lane = tid & 31;
    const int bh   = blockIdx.y;
    const int qt   = blockIdx.x;
    const __half* kb = k + (size_t)bh * SEQ * Dd;
    const __half* vb = v + (size_t)bh * SEQ * Dd;
    const __half* qb = q + ((size_t)bh * SEQ + qt * 128) * Dd;

    // stage Q (128x64 halfs) + K/V tile 0
    {
        int r = tid >> 1, c0 = (tid & 1) * 32;
        #pragma unroll
        for (int i = 0; i < 4; i++)
            cp_async16(&Qs[r * QLD + c0 + i * 8], &qb[(size_t)r * Dd + c0 + i * 8]);
        int lr = tid >> 2, lc = (tid & 3) * 16;
        #pragma unroll
        for (int i = 0; i < 2; i++) {
            cp_async16(&Ks[lr * QLD + lc + i * 8], &kb[(size_t)lr * Dd + lc + i * 8]);
            cp_async16(&Vs[lr * QLD + lc + i * 8], &vb[(size_t)lr * Dd + lc + i * 8]);
        }
        cp_commit();
    }

    const uint32_t qs_b = (uint32_t)__cvta_generic_to_shared(Qs);
    const uint32_t ks_b = (uint32_t)__cvta_generic_to_shared(Ks);
    const uint32_t vs_b = (uint32_t)__cvta_generic_to_shared(Vs);

    cp_wait<0>();
    __syncthreads();

    // Q A-fragments: 4 k-chunks of 16
    uint32_t qa[4][4];
    {
        int r = w * 16 + (lane & 15);
        int cbase = 8 * (lane >> 4);
        #pragma unroll
        for (int kk = 0; kk < 4; kk++)
            ldsm_x4(qa[kk], qs_b + (uint32_t)(r * QLD + kk * 16 + cbase) * 2);
    }

    float oacc[8][4];
    #pragma unroll
    for (int i = 0; i < 8; i++)
        #pragma unroll
        for (int j = 0; j < 4; j++) oacc[i][j] = 0.f;
    float l0 = 0.f, l1 = 0.f;

    const int colb  = 2 * (lane & 3);
    const int row0g = qt * 128 + w * 16 + (lane >> 2);   // global q row (c0,c1)

    // ldmatrix address components
    const int kK_row = (lane & 7) + 8 * (lane >> 4);        // + n0
    const int kK_col = 8 * ((lane >> 3) & 1);               // + d0
    const int vV_row = (lane & 7) + 8 * ((lane >> 3) & 1);  // + k0
    const int vV_col = 8 * (lane >> 4);                     // + d0

    const int NT = SEQ / 64;
    for (int t = 0; t < NT; t++) {
        const int s  = t & 1;
        const int kt = t * 64;

        if (t + 1 < NT) {
            const int kn = kt + 64;
            __half* Kd = &Ks[(s ^ 1) * FTILE];
            __half* Vd = &Vs[(s ^ 1) * FTILE];
            int lr = tid >> 2, lc = (tid & 3) * 16;
            #pragma unroll
            for (int i = 0; i < 2; i++) {
                cp_async16(&Kd[lr * QLD + lc + i * 8], &kb[(size_t)(kn + lr) * Dd + lc + i * 8]);
                cp_async16(&Vd[lr * QLD + lc + i * 8], &vb[(size_t)(kn + lr) * Dd + lc + i * 8]);
            }
            cp_commit();
            cp_wait<1>();
        } else {
            cp_wait<0>();
        }
        __syncthreads();

        const uint32_t ks_s = ks_b + (uint32_t)(s * FTILE) * 2;
        const uint32_t vs_s = vs_b + (uint32_t)(s * FTILE) * 2;

        // ---- S = Q @ K^T : sfr[8][4] in registers ----
        float sfr[8][4];
        #pragma unroll
        for (int i = 0; i < 8; i++)
            #pragma unroll
            for (int j = 0; j < 4; j++) sfr[i][j] = 0.f;

        #pragma unroll
        for (int kk = 0; kk < 4; kk++) {
            const int d0 = kk * 16;
            #pragma unroll
            for (int np = 0; np < 4; np++) {
                uint32_t kr[4];
                ldsm_x4(kr, ks_s + (uint32_t)((np * 16 + kK_row) * QLD + d0 + kK_col) * 2);
                mma16816(sfr[2 * np],     qa[kk], kr);
                mma16816(sfr[2 * np + 1], qa[kk], kr + 2);
            }
        }

        // ---- P = exp(S - 3 + tril) in registers; pack to half A-frags ----
        uint32_t pa[4][4];
        #pragma unroll
        for (int nt = 0; nt < 8; nt++) {
            int col = kt + nt * 8 + colb;
            float p0 = __expf(sfr[nt][0] - 3.f + ((col    ) <= row0g     ? 1.f : 0.f));
            float p1 = __expf(sfr[nt][1] - 3.f + ((col + 1) <= row0g     ? 1.f : 0.f));
            float p2 = __expf(sfr[nt][2] - 3.f + ((col    ) <= row0g + 8 ? 1.f : 0.f));
            float p3 = __expf(sfr[nt][3] - 3.f + ((col + 1) <= row0g + 8 ? 1.f : 0.f));
            l0 += p0 + p1;
            l1 += p2 + p3;
            pa[nt >> 1][(nt & 1) * 2]     = packh2(p0, p1);
            pa[nt >> 1][(nt & 1) * 2 + 1] = packh2(p2, p3);
        }

        // ---- O += P @ V ----
        #pragma unroll
        for (int kk = 0; kk < 4; kk++) {
            const int k0 = kk * 16;
            #pragma unroll
            for (int dp = 0; dp < 4; dp++) {
                const int d0 = dp * 16;
                uint32_t vr[4];
                ldsm_x4_t(vr, vs_s + (uint32_t)((k0 + vV_row) * QLD + d0 + vV_col) * 2);
                mma16816(oacc[2 * dp],     pa[kk], vr);
                mma16816(oacc[2 * dp + 1], pa[kk], vr + 2);
            }
        }
        __syncthreads();
    }

    // ---- epilogue: reduce l over the 4 lanes of each row group, write out ----
    l0 += __shfl_xor_sync(0xffffffffu, l0, 1);
    l0 += __shfl_xor_sync(0xffffffffu, l0, 2);
    l1 += __shfl_xor_sync(0xffffffffu, l1, 1);
    l1 += __shfl_xor_sync(0xffffffffu, l1, 2);
    const float invl0 = 1.f / l0, invl1 = 1.f / l1;

    const int b = bh >> 4, h = bh & 15;
    const int r0 = qt * 128 + w * 16 + (lane >> 2);
    __half* d0p = out + ((size_t)(b * SEQ + r0    )) * Hh + h * Dd;
    __half* d1p = out + ((size_t)(b * SEQ + r0 + 8)) * Hh + h * Dd;
    #pragma unroll
    for (int nt = 0; nt < 8; nt++) {
        int col = nt * 8 + colb;
        *(__half2*)&d0p[col] = __floats2half2_rn(oacc[nt][0] * invl0, oacc[nt][1] * invl0);
        *(__half2*)&d1p[col] = __floats2half2_rn(oacc[nt][2] * invl1, oacc[nt][3] * invl1);
    }
}

// ---------------------------------------------------------------------------
extern "C" void kernel_launch(void* const* d_in, const int* in_sizes, int n_in,
                              void* d_out, int out_size)
{
    const float* hs   = (const float*)d_in[0];
    const float* cosT = (const float*)d_in[1];
    const float* sinT = (const float*)d_in[2];
    const float* Wq   = (const float*)d_in[3];
    const float* bq   = (const float*)d_in[4];
    const float* Wk   = (const float*)d_in[5];
    const float* bk   = (const float*)d_in[6];
    const float* Wv   = (const float*)d_in[7];
    const float* bv   = (const float*)d_in[8];
    const float* Wo   = (const float*)d_in[9];
    const float* bo   = (const float*)d_in[10];
    const float* rw   = (const float*)d_in[11];
    float* out = (float*)d_out;

    float* f32 = nullptr;  cudaGetSymbolAddress((void**)&f32, g_f32);
    __half* f16 = nullptr; cudaGetSymbolAddress((void**)&f16, g_f16);

    const size_t SZ = SZc;
    const size_t WZ = WZc;
    float* qlin = f32;
    float* klin = f32 + SZ;
    float* vlin = f32 + 2 * SZ;

    __half* hs_h  = f16;
    __half* Wq_h  = f16 + SZ;
    __half* Wk_h  = Wq_h + WZ;
    __half* Wv_h  = Wk_h + WZ;
    __half* Wo_h  = Wv_h + WZ;
    __half* qT    = Wo_h + WZ;
    __half* kT    = qT + SZ;
    __half* vT    = kT + SZ;
    __half* attn  = vT + SZ;

    cudaFuncSetAttribute(flash_mma_kernel,
                         cudaFuncAttributeMaxDynamicSharedMemorySize, FSM_BYTES);
    cudaFuncSetAttribute(gemm_fp16_kernel,
                         cudaFuncAttributeMaxDynamicSharedMemorySize, GEMM_SMEM);

    f2h_all_kernel<<<(int)((SZ + 4 * WZ) / 1024), 256>>>(hs, Wq, Wk, Wv, Wo, f16);

    dim3 gqkv(Hh / 128, Mtok / 128, 3);
    gemm_fp16_kernel<<<gqkv, 256, GEMM_SMEM>>>(hs_h, Wq_h, Wk_h, Wv_h,
                                               qlin, klin, vlin, nullptr);

    normrope_kernel<<<Mtok, 256>>>(qlin, klin, vlin, bq, bk, bv,
                                   cosT, sinT, rw, qT, kT, vT);

    dim3 fg(SEQ / 128, Bb * NHd);
    flash_mma_kernel<<<fg, 256, FSM_BYTES>>>(qT, kT, vT, attn);

    dim3 gout(Hh / 128, Mtok / 128, 1);
    gemm_fp16_kernel<<<gout, 256, GEMM_SMEM>>>(attn, Wo_h, Wo_h, Wo_h,
                                               out, out, out, bo);
}

// round 8
// speedup vs baseline: 1.2626x; 1.0673x over previous
#include <cuda_runtime.h>
#include <cuda_fp16.h>
#include <mma.h>
#include <math.h>
#include <stdint.h>

using namespace nvcuda;

#define Bb    2
#define SEQ   2048
#define Hh    1024
#define NHd   16
#define Dd    64
#define Mtok  4096

__device__ float  g_f32[(size_t)3 * Mtok * Hh];   // reused as half qlin/klin/vlin
__device__ __half g_f16[(size_t)(4 + 4 + 12 + 4) * 1024 * 1024];

__device__ __forceinline__ void cp_async16(void* smem, const void* gmem) {
    unsigned saddr = (unsigned)__cvta_generic_to_shared(smem);
    asm volatile("cp.async.cg.shared.global [%0], [%1], 16;\n" :: "r"(saddr), "l"(gmem));
}
__device__ __forceinline__ void cp_commit() { asm volatile("cp.async.commit_group;\n"); }
template <int N>
__device__ __forceinline__ void cp_wait() { asm volatile("cp.async.wait_group %0;\n" :: "n"(N)); }

__device__ __forceinline__ void ldsm_x4(uint32_t* r, uint32_t saddr) {
    asm volatile("ldmatrix.sync.aligned.m8n8.x4.shared.b16 {%0,%1,%2,%3}, [%4];"
                 : "=r"(r[0]), "=r"(r[1]), "=r"(r[2]), "=r"(r[3]) : "r"(saddr));
}
__device__ __forceinline__ void ldsm_x4_t(uint32_t* r, uint32_t saddr) {
    asm volatile("ldmatrix.sync.aligned.m8n8.x4.trans.shared.b16 {%0,%1,%2,%3}, [%4];"
                 : "=r"(r[0]), "=r"(r[1]), "=r"(r[2]), "=r"(r[3]) : "r"(saddr));
}
__device__ __forceinline__ void mma16816(float* c, const uint32_t* a, const uint32_t* b) {
    asm volatile(
        "mma.sync.aligned.m16n8k16.row.col.f32.f16.f16.f32 "
        "{%0,%1,%2,%3}, {%4,%5,%6,%7}, {%8,%9}, {%0,%1,%2,%3};"
        : "+f"(c[0]), "+f"(c[1]), "+f"(c[2]), "+f"(c[3])
        : "r"(a[0]), "r"(a[1]), "r"(a[2]), "r"(a[3]), "r"(b[0]), "r"(b[1]));
}
__device__ __forceinline__ uint32_t packh2(float x, float y) {
    __half2 h = __floats2half2_rn(x, y);
    return *(uint32_t*)&h;
}
__device__ __forceinline__ float ex2f(float x) {
    float y; asm("ex2.approx.f32 %0, %1;" : "=f"(y) : "f"(x)); return y;
}

// ---------------------------------------------------------------------------
// fused fp32->fp16 conversion
// ---------------------------------------------------------------------------
#define SZc ((size_t)Mtok * Hh)
#define WZc ((size_t)Hh * Hh)
__global__ __launch_bounds__(256)
void f2h_all_kernel(const float* __restrict__ hs,
                    const float* __restrict__ Wq, const float* __restrict__ Wk,
                    const float* __restrict__ Wv, const float* __restrict__ Wo,
                    __half* __restrict__ dst)
{
    size_t i4 = ((size_t)blockIdx.x * 256 + threadIdx.x) * 4;
    const float* s;
    if (i4 < SZc) s = &hs[i4];
    else {
        size_t wo = i4 - SZc;
        s = (wo < WZc)     ? &Wq[wo]
          : (wo < 2 * WZc) ? &Wk[wo - WZc]
          : (wo < 3 * WZc) ? &Wv[wo - 2 * WZc]
                           : &Wo[wo - 3 * WZc];
    }
    float4 v = *(const float4*)s;
    *(__half2*)&dst[i4]     = __floats2half2_rn(v.x, v.y);
    *(__half2*)&dst[i4 + 2] = __floats2half2_rn(v.z, v.w);
}

// ---------------------------------------------------------------------------
// fp16 GEMM: 128x128 tile, BK=32, 3-stage cp.async, 256 threads, 8 warps.
// Half-output mode (H0..H2, z-select) OR float-output with bias (F).
// ---------------------------------------------------------------------------
#define GBK  32
#define GLD3 40                      // halfs per row (32 + 8 pad)
#define GSTG (128 * GLD3)            // halfs per matrix per stage
#define CLD  132
#define GEMM_SMEM (132 * 128 * 4)    // 67584 B (>= 6*GSTG*2 = 61440)
#define NITER 32

__global__ __launch_bounds__(256)
void gemm_fp16_kernel(const __half* __restrict__ A,
                      const __half* __restrict__ W0, const __half* __restrict__ W1,
                      const __half* __restrict__ W2,
                      __half* __restrict__ H0, __half* __restrict__ H1,
                      __half* __restrict__ H2,
                      float* __restrict__ F, const float* __restrict__ bias)
{
    extern __shared__ __align__(16) __half gsm[];
    __half* As = gsm;                  // [3][GSTG]
    __half* Bs = gsm + 3 * GSTG;       // [3][GSTG]

    const __half* W = (blockIdx.z == 0) ? W0 : (blockIdx.z == 1) ? W1 : W2;
    __half*       H = (blockIdx.z == 0) ? H0 : (blockIdx.z == 1) ? H1 : H2;

    const int tid = threadIdx.x;
    const int bm = blockIdx.y * 128, bn = blockIdx.x * 128;
    const int w  = tid >> 5;
    const int wr = w & 3;
    const int wc = w >> 2;
    const int K = 1024;

    wmma::fragment<wmma::accumulator, 16, 16, 16, float> acc[2][4];
    #pragma unroll
    for (int i = 0; i < 2; i++)
        #pragma unroll
        for (int j = 0; j < 4; j++) wmma::fill_fragment(acc[i][j], 0.0f);

    const int lr = tid >> 2;           // 0..63
    const int lc = (tid & 3) * 8;      // 0,8,16,24

    // prefetch stages 0,1
    #pragma unroll
    for (int st = 0; st < 2; st++) {
        const int k0 = st * GBK;
        #pragma unroll
        for (int i = 0; i < 2; i++) {
            int r = lr + i * 64;
            cp_async16(&As[st * GSTG + r * GLD3 + lc], &A[(size_t)(bm + r) * K + k0 + lc]);
            cp_async16(&Bs[st * GSTG + r * GLD3 + lc], &W[(size_t)(bn + r) * K + k0 + lc]);
        }
        cp_commit();
    }

    int sidx = 0;
    for (int it = 0; it < NITER; it++) {
        if (it < NITER - 1) cp_wait<1>(); else cp_wait<0>();
        __syncthreads();

        if (it + 2 < NITER) {
            const int st = (sidx + 2 >= 3) ? sidx - 1 : sidx + 2;
            const int k0 = (it + 2) * GBK;
            #pragma unroll
            for (int i = 0; i < 2; i++) {
                int r = lr + i * 64;
                cp_async16(&As[st * GSTG + r * GLD3 + lc], &A[(size_t)(bm + r) * K + k0 + lc]);
                cp_async16(&Bs[st * GSTG + r * GLD3 + lc], &W[(size_t)(bn + r) * K + k0 + lc]);
            }
            cp_commit();
        }

        const __half* Ac = &As[sidx * GSTG];
        const __half* Bc = &Bs[sidx * GSTG];
        #pragma unroll
        for (int kk = 0; kk < 2; kk++) {
            const int kd = kk * 16;
            wmma::fragment<wmma::matrix_a, 16, 16, 16, __half, wmma::row_major> a0, a1;
            wmma::load_matrix_sync(a0, &Ac[(wr * 32     ) * GLD3 + kd], GLD3);
            wmma::load_matrix_sync(a1, &Ac[(wr * 32 + 16) * GLD3 + kd], GLD3);
            #pragma unroll
            for (int nt = 0; nt < 4; nt++) {
                wmma::fragment<wmma::matrix_b, 16, 16, 16, __half, wmma::col_major> b;
                wmma::load_matrix_sync(b, &Bc[(wc * 64 + nt * 16) * GLD3 + kd], GLD3);
                wmma::mma_sync(acc[0][nt], a0, b, acc[0][nt]);
                wmma::mma_sync(acc[1][nt], a1, b, acc[1][nt]);
            }
        }
        sidx = (sidx + 1 >= 3) ? 0 : sidx + 1;
    }

    // epilogue via smem staging
    __syncthreads();
    float* Cs = (float*)gsm;
    #pragma unroll
    for (int i = 0; i < 2; i++)
        #pragma unroll
        for (int j = 0; j < 4; j++)
            wmma::store_matrix_sync(&Cs[(wr * 32 + i * 16) * CLD + wc * 64 + j * 16],
                                    acc[i][j], CLD, wmma::mem_row_major);
    __syncthreads();

    const int row = tid >> 1;
    const int cb  = (tid & 1) * 64;
    const float* src = &Cs[row * CLD + cb];
    if (H != nullptr) {
        __half* dst = &H[(size_t)(bm + row) * 1024 + bn + cb];
        #pragma unroll
        for (int j = 0; j < 64; j += 4) {
            float4 o = *(const float4*)&src[j];
            *(__half2*)&dst[j]     = __floats2half2_rn(o.x, o.y);
            *(__half2*)&dst[j + 2] = __floats2half2_rn(o.z, o.w);
        }
    } else {
        float* dst = &F[(size_t)(bm + row) * 1024 + bn + cb];
        const float* bp = &bias[bn + cb];
        #pragma unroll
        for (int j = 0; j < 64; j += 4) {
            float4 o = *(const float4*)&src[j];
            o.x += bp[j]; o.y += bp[j + 1]; o.z += bp[j + 2]; o.w += bp[j + 3];
            *(float4*)&dst[j] = o;
        }
    }
}

// ---------------------------------------------------------------------------
// RMSNorm + bias + RoPE from HALF qlin/klin/vlin; half q/k/v out [B,NH,S,D].
// q is pre-scaled by 0.125*log2(e) so flash can use exp2 directly.
// ---------------------------------------------------------------------------
#define QSCALE (0.125f * 1.44269504089f)

__global__ __launch_bounds__(256)
void normrope_kernel(const __half* __restrict__ qlin, const __half* __restrict__ klin,
                     const __half* __restrict__ vlin,
                     const float* __restrict__ bq, const float* __restrict__ bk,
                     const float* __restrict__ bv,
                     const float* __restrict__ cosT, const float* __restrict__ sinT,
                     const float* __restrict__ w,
                     __half* __restrict__ qo, __half* __restrict__ ko, __half* __restrict__ vo)
{
    const int t = blockIdx.x;
    const int b = t >> 11;
    const int s = t & 2047;
    const int tid = threadIdx.x;

    __shared__ float sq[1024], sk[1024];
    __shared__ float red[16];
    __shared__ float rqs, rks;

    float sumq = 0.f, sumk = 0.f;
    for (int i = tid; i < 1024; i += 256) {
        float x = __half2float(qlin[(size_t)t * 1024 + i]) + bq[i]; sq[i] = x; sumq += x * x;
        float y = __half2float(klin[(size_t)t * 1024 + i]) + bk[i]; sk[i] = y; sumk += y * y;
    }
    #pragma unroll
    for (int off = 16; off > 0; off >>= 1) {
        sumq += __shfl_down_sync(0xffffffffu, sumq, off);
        sumk += __shfl_down_sync(0xffffffffu, sumk, off);
    }
    if ((tid & 31) == 0) { red[tid >> 5] = sumq; red[8 + (tid >> 5)] = sumk; }
    __syncthreads();
    if (tid == 0) {
        float a = 0.f, c = 0.f;
        #pragma unroll
        for (int i2 = 0; i2 < 8; i2++) { a += red[i2]; c += red[8 + i2]; }
        rqs = rsqrtf(a * (1.0f / 1024.0f) + 1e-6f);
        rks = rsqrtf(c * (1.0f / 1024.0f) + 1e-6f);
    }
    __syncthreads();
    const float rq = rqs, rk = rks;

    for (int i = tid; i < 1024; i += 256) {
        int h = i >> 6, d = i & 63;
        float cs = cosT[s * 64 + d], sn = sinT[s * 64 + d];
        int   pi = (d < 32) ? i + 32 : i - 32;
        float sign = (d < 32) ? -1.f : 1.f;
        float wv = w[i], wp = w[pi];
        float qv = sq[i] * rq * wv, qp = sq[pi] * rq * wp;
        float kv = sk[i] * rk * wv, kp = sk[pi] * rk * wp;
        size_t oidx = ((size_t)(b * NHd + h) * SEQ + s) * Dd + d;
        qo[oidx] = __float2half((qv * cs + sign * qp * sn) * QSCALE);
        ko[oidx] = __float2half(kv * cs + sign * kp * sn);
        vo[oidx] = __float2half(__half2float(vlin[(size_t)t * 1024 + i]) + bv[i]);
    }
}

// ---------------------------------------------------------------------------
// Flash attention, raw mma.sync, register-resident S/P, exp2-domain scores.
// p = 2^(S + c), c = (col<=row) ? -2*log2e : -3*log2e  (tril +1, -3 shift).
// ---------------------------------------------------------------------------
#define QLD 72
#define FTILE (64 * QLD)
#define FSM_BYTES ((128 * QLD + 4 * FTILE) * 2)
#define C_IN  (-2.88539008178f)     // (1-3)*log2e
#define C_OUT (-4.32808512267f)     // (0-3)*log2e

__global__ __launch_bounds__(256, 2)
void flash_mma_kernel(const __half* __restrict__ q, const __half* __restrict__ k,
                      const __half* __restrict__ v, __half* __restrict__ out)
{
    extern __shared__ __align__(16) char smraw[];
    __half* Qs = (__half*)smraw;
    __half* Ks = Qs + 128 * QLD;
    __half* Vs = Ks + 2 * FTILE;

    const int tid  = threadIdx.x;
    const int w    = tid >> 5;
    const int lane = tid & 31;
    const int bh   = blockIdx.y;
    const int qt   = blockIdx.x;
    const __half* kb = k + (size_t)bh * SEQ * Dd;
    const __half* vb = v + (size_t)bh * SEQ * Dd;
    const __half* qb = q + ((size_t)bh * SEQ + qt * 128) * Dd;

    {
        int r = tid >> 1, c0 = (tid & 1) * 32;
        #pragma unroll
        for (int i = 0; i < 4; i++)
            cp_async16(&Qs[r * QLD + c0 + i * 8], &qb[(size_t)r * Dd + c0 + i * 8]);
        int lr = tid >> 2, lc = (tid & 3) * 16;
        #pragma unroll
        for (int i = 0; i < 2; i++) {
            cp_async16(&Ks[lr * QLD + lc + i * 8], &kb[(size_t)lr * Dd + lc + i * 8]);
            cp_async16(&Vs[lr * QLD + lc + i * 8], &vb[(size_t)lr * Dd + lc + i * 8]);
        }
        cp_commit();
    }

    const uint32_t qs_b = (uint32_t)__cvta_generic_to_shared(Qs);
    const uint32_t ks_b = (uint32_t)__cvta_generic_to_shared(Ks);
    const uint32_t vs_b = (uint32_t)__cvta_generic_to_shared(Vs);

    cp_wait<0>();
    __syncthreads();

    uint32_t qa[4][4];
    {
        int r = w * 16 + (lane & 15);
        int cbase = 8 * (lane >> 4);
        #pragma unroll
        for (int kk = 0; kk < 4; kk++)
            ldsm_x4(qa[kk], qs_b + (uint32_t)(r * QLD + kk * 16 + cbase) * 2);
    }

    float oacc[8][4];
    #pragma unroll
    for (int i = 0; i < 8; i++)
        #pragma unroll
        for (int j = 0; j < 4; j++) oacc[i][j] = 0.f;
    float l0 = 0.f, l1 = 0.f;

    const int colb  = 2 * (lane & 3);
    const int row0g = qt * 128 + w * 16 + (lane >> 2);

    const int kK_row = (lane & 7) + 8 * (lane >> 4);
    const int kK_col = 8 * ((lane >> 3) & 1);
    const int vV_row = (lane & 7) + 8 * ((lane >> 3) & 1);
    const int vV_col = 8 * (lane >> 4);

    const int NT = SEQ / 64;
    for (int t = 0; t < NT; t++) {
        const int s  = t & 1;
        const int kt = t * 64;

        if (t + 1 < NT) {
            const int kn = kt + 64;
            __half* Kd = &Ks[(s ^ 1) * FTILE];
            __half* Vd = &Vs[(s ^ 1) * FTILE];
            int lr = tid >> 2, lc = (tid & 3) * 16;
            #pragma unroll
            for (int i = 0; i < 2; i++) {
                cp_async16(&Kd[lr * QLD + lc + i * 8], &kb[(size_t)(kn + lr) * Dd + lc + i * 8]);
                cp_async16(&Vd[lr * QLD + lc + i * 8], &vb[(size_t)(kn + lr) * Dd + lc + i * 8]);
            }
            cp_commit();
            cp_wait<1>();
        } else {
            cp_wait<0>();
        }
        __syncthreads();

        const uint32_t ks_s = ks_b + (uint32_t)(s * FTILE) * 2;
        const uint32_t vs_s = vs_b + (uint32_t)(s * FTILE) * 2;

        float sfr[8][4];
        #pragma unroll
        for (int i = 0; i < 8; i++)
            #pragma unroll
            for (int j = 0; j < 4; j++) sfr[i][j] = 0.f;

        #pragma unroll
        for (int kk = 0; kk < 4; kk++) {
            const int d0 = kk * 16;
            #pragma unroll
            for (int np = 0; np < 4; np++) {
                uint32_t kr[4];
                ldsm_x4(kr, ks_s + (uint32_t)((np * 16 + kK_row) * QLD + d0 + kK_col) * 2);
                mma16816(sfr[2 * np],     qa[kk], kr);
                mma16816(sfr[2 * np + 1], qa[kk], kr + 2);
            }
        }

        uint32_t pa[4][4];
        #pragma unroll
        for (int nt = 0; nt < 8; nt++) {
            int col = kt + nt * 8 + colb;
            float p0 = ex2f(sfr[nt][0] + ((col    ) <= row0g     ? C_IN : C_OUT));
            float p1 = ex2f(sfr[nt][1] + ((col + 1) <= row0g     ? C_IN : C_OUT));
            float p2 = ex2f(sfr[nt][2] + ((col    ) <= row0g + 8 ? C_IN : C_OUT));
            float p3 = ex2f(sfr[nt][3] + ((col + 1) <= row0g + 8 ? C_IN : C_OUT));
            l0 += p0 + p1;
            l1 += p2 + p3;
            pa[nt >> 1][(nt & 1) * 2]     = packh2(p0, p1);
            pa[nt >> 1][(nt & 1) * 2 + 1] = packh2(p2, p3);
        }

        #pragma unroll
        for (int kk = 0; kk < 4; kk++) {
            const int k0 = kk * 16;
            #pragma unroll
            for (int dp = 0; dp < 4; dp++) {
                const int d0 = dp * 16;
                uint32_t vr[4];
                ldsm_x4_t(vr, vs_s + (uint32_t)((k0 + vV_row) * QLD + d0 + vV_col) * 2);
                mma16816(oacc[2 * dp],     pa[kk], vr);
                mma16816(oacc[2 * dp + 1], pa[kk], vr + 2);
            }
        }
        __syncthreads();
    }

    l0 += __shfl_xor_sync(0xffffffffu, l0, 1);
    l0 += __shfl_xor_sync(0xffffffffu, l0, 2);
    l1 += __shfl_xor_sync(0xffffffffu, l1, 1);
    l1 += __shfl_xor_sync(0xffffffffu, l1, 2);
    const float invl0 = 1.f / l0, invl1 = 1.f / l1;

    const int b = bh >> 4, h = bh & 15;
    const int r0 = qt * 128 + w * 16 + (lane >> 2);
    __half* d0p = out + ((size_t)(b * SEQ + r0    )) * Hh + h * Dd;
    __half* d1p = out + ((size_t)(b * SEQ + r0 + 8)) * Hh + h * Dd;
    #pragma unroll
    for (int nt = 0; nt < 8; nt++) {
        int col = nt * 8 + colb;
        *(__half2*)&d0p[col] = __floats2half2_rn(oacc[nt][0] * invl0, oacc[nt][1] * invl0);
        *(__half2*)&d1p[col] = __floats2half2_rn(oacc[nt][2] * invl1, oacc[nt][3] * invl1);
    }
}

// ---------------------------------------------------------------------------
extern "C" void kernel_launch(void* const* d_in, const int* in_sizes, int n_in,
                              void* d_out, int out_size)
{
    const float* hs   = (const float*)d_in[0];
    const float* cosT = (const float*)d_in[1];
    const float* sinT = (const float*)d_in[2];
    const float* Wq   = (const float*)d_in[3];
    const float* bq   = (const float*)d_in[4];
    const float* Wk   = (const float*)d_in[5];
    const float* bk   = (const float*)d_in[6];
    const float* Wv   = (const float*)d_in[7];
    const float* bv   = (const float*)d_in[8];
    const float* Wo   = (const float*)d_in[9];
    const float* bo   = (const float*)d_in[10];
    const float* rw   = (const float*)d_in[11];
    float* out = (float*)d_out;

    float* f32 = nullptr;  cudaGetSymbolAddress((void**)&f32, g_f32);
    __half* f16 = nullptr; cudaGetSymbolAddress((void**)&f16, g_f16);

    const size_t SZ = SZc;
    const size_t WZ = WZc;
    // half views of the (otherwise unused) fp32 scratch for qlin/klin/vlin
    __half* qlinH = (__half*)f32;
    __half* klinH = qlinH + SZ;
    __half* vlinH = klinH + SZ;

    __half* hs_h  = f16;
    __half* Wq_h  = f16 + SZ;
    __half* Wk_h  = Wq_h + WZ;
    __half* Wv_h  = Wk_h + WZ;
    __half* Wo_h  = Wv_h + WZ;
    __half* qT    = Wo_h + WZ;
    __half* kT    = qT + SZ;
    __half* vT    = kT + SZ;
    __half* attn  = vT + SZ;

    cudaFuncSetAttribute(flash_mma_kernel,
                         cudaFuncAttributeMaxDynamicSharedMemorySize, FSM_BYTES);
    cudaFuncSetAttribute(gemm_fp16_kernel,
                         cudaFuncAttributeMaxDynamicSharedMemorySize, GEMM_SMEM);

    f2h_all_kernel<<<(int)((SZ + 4 * WZ) / 1024), 256>>>(hs, Wq, Wk, Wv, Wo, f16);

    dim3 gqkv(Hh / 128, Mtok / 128, 3);
    gemm_fp16_kernel<<<gqkv, 256, GEMM_SMEM>>>(hs_h, Wq_h, Wk_h, Wv_h,
                                               qlinH, klinH, vlinH,
                                               nullptr, nullptr);

    normrope_kernel<<<Mtok, 256>>>(qlinH, klinH, vlinH, bq, bk, bv,
                                   cosT, sinT, rw, qT, kT, vT);

    dim3 fg(SEQ / 128, Bb * NHd);
    flash_mma_kernel<<<fg, 256, FSM_BYTES>>>(qT, kT, vT, attn);

    dim3 gout(Hh / 128, Mtok / 128, 1);
    gemm_fp16_kernel<<<gout, 256, GEMM_SMEM>>>(attn, Wo_h, Wo_h, Wo_h,
                                               nullptr, nullptr, nullptr,
                                               out, bo);
}